// round 12
// baseline (speedup 1.0000x reference)
#include <cuda_runtime.h>

// GINConv N=2048, F=32, E=16, K=32, adj density ~5%.
// Output tuple layout: [adj N*N][out N*K][edges N*N*E], all fp32.
//
// Structure (this round):
//   - The 256MB edges pass-through is a cudaMemcpyAsync D2D graph node
//     (driver SOL copy; removes 512MB of traffic from hand-written code).
//   - One small compute kernel (block per row): adj streaming copy +
//     ballot compaction, sparse relu-message via shfl-broadcast GEMVs
//     (adj nonzeros are exactly 1.0f), epilogue GEMVs with W_n/W_net read
//     straight from L2 (keeps smem ~11KB -> ~8 blocks/SM occupancy).

#define NN 2048
#define FF 32
#define EE 16
#define KK 32

#define OUT_OFF   ((size_t)NN * NN)
#define EDGE_OFF  ((size_t)NN * NN + (size_t)NN * KK)

__global__ void __launch_bounds__(256) ginconv_compute(
    const float* __restrict__ adj,   const float* __restrict__ nodes,
    const float* __restrict__ edges,
    const float* __restrict__ W_ne,  const float* __restrict__ b_ne,
    const float* __restrict__ W_n,   const float* __restrict__ b_n,
    const float* __restrict__ W_net, const float* __restrict__ b_net,
    const float* __restrict__ eps,   float* __restrict__ out)
{
    __shared__ float sW1[FF * FF];        // W_ne rows 0..F-1   (node slice) 4KB
    __shared__ float sWe[EE * FF];        // W_ne rows F..F+E-1 (edge slice) 2KB
    __shared__ float sbne[FF];
    __shared__ float spart[8 * FF];       // per-warp message partials       1KB
    __shared__ float spre[FF];
    __shared__ unsigned short snbr[NN];   // compacted neighbor ids          4KB
    __shared__ int scnt;

    const int tid  = threadIdx.x;
    const int row  = blockIdx.x;
    const int wrp  = tid >> 5;
    const int lane = tid & 31;

    // stage W_ne ([(F+E), F] row-major: node rows then edge rows, contiguous)
    for (int t = tid; t < (FF + EE) * FF; t += 256) {
        float v = W_ne[t];
        if (t < FF * FF) sW1[t] = v;
        else             sWe[t - FF * FF] = v;
    }
    if (tid < FF) sbne[tid] = b_ne[tid];
    if (tid == 0) scnt = 0;
    __syncthreads();

    // adj row: streaming copy + warp-ballot compaction (message sum is
    // order-free, so compaction order across warps does not matter)
    {
        const float4* src = (const float4*)(adj + (size_t)row * NN);
        float4*       dst = (float4*)(out + (size_t)row * NN);
        const unsigned ltmask = (1u << lane) - 1u;
#pragma unroll
        for (int it = 0; it < 2; ++it) {
            int idx = tid + it * 256;          // 512 float4 = 2048 floats
            float4 a = __ldcs(src + idx);
            __stcs(dst + idx, a);
            unsigned m0 = __ballot_sync(0xffffffffu, a.x != 0.f);
            unsigned m1 = __ballot_sync(0xffffffffu, a.y != 0.f);
            unsigned m2 = __ballot_sync(0xffffffffu, a.z != 0.f);
            unsigned m3 = __ballot_sync(0xffffffffu, a.w != 0.f);
            int tot = __popc(m0) + __popc(m1) + __popc(m2) + __popc(m3);
            int base = 0;
            if (lane == 0 && tot) base = atomicAdd(&scnt, tot);
            base = __shfl_sync(0xffffffffu, base, 0);
            int jb = idx * 4;
            if (a.x != 0.f) snbr[base + __popc(m0 & ltmask)] = (unsigned short)(jb);
            base += __popc(m0);
            if (a.y != 0.f) snbr[base + __popc(m1 & ltmask)] = (unsigned short)(jb + 1);
            base += __popc(m1);
            if (a.z != 0.f) snbr[base + __popc(m2 & ltmask)] = (unsigned short)(jb + 2);
            base += __popc(m2);
            if (a.w != 0.f) snbr[base + __popc(m3 & ltmask)] = (unsigned short)(jb + 3);
        }
    }
    __syncthreads();

    // sparse message: warp per neighbor j, lane = output feature f
    {
        const int nnz = scnt;
        const float* erow = edges + (size_t)row * NN * EE;
        float acc = 0.f;
        for (int n = wrp; n < nnz; n += 8) {
            int j = snbr[n];
            float xg = nodes[j * FF + lane];               // node feature g=lane
            float ev = erow[j * EE + (lane & (EE - 1))];   // edge feats lanes 0..15
            float s = sbne[lane];
#pragma unroll
            for (int g = 0; g < FF; ++g)
                s = fmaf(__shfl_sync(0xffffffffu, xg, g), sW1[g * FF + lane], s);
#pragma unroll
            for (int e = 0; e < EE; ++e)
                s = fmaf(__shfl_sync(0xffffffffu, ev, e), sWe[e * FF + lane], s);
            acc += fmaxf(s, 0.f);                          // adj value == 1.0f
        }
        spart[wrp * FF + lane] = acc;
    }
    __syncthreads();

    // epilogue on warp 0: W_n / W_net read straight from global (L2-resident;
    // keeps smem small so the block-residency stays high)
    if (wrp == 0) {
        float msg = 0.f;
#pragma unroll
        for (int w = 0; w < 8; ++w) msg += spart[w * FF + lane];
        float xi = nodes[(size_t)row * FF + lane];
        float t = __ldg(b_n + lane);
#pragma unroll
        for (int g = 0; g < FF; ++g)
            t = fmaf(__shfl_sync(0xffffffffu, xi, g), __ldg(W_n + g * FF + lane), t);
        spre[lane] = (1.f + __ldg(eps)) * fmaxf(t, 0.f) + msg;
        __syncwarp();
        float o = __ldg(b_net + lane);
#pragma unroll
        for (int f = 0; f < FF; ++f)
            o = fmaf(spre[f], __ldg(W_net + f * KK + lane), o);
        out[OUT_OFF + (size_t)row * KK + lane] = fmaxf(o, 0.f);
    }
}

extern "C" void kernel_launch(void* const* d_in, const int* in_sizes, int n_in,
                              void* d_out, int out_size)
{
    const float* adj   = (const float*)d_in[0];
    const float* nodes = (const float*)d_in[1];
    const float* edges = (const float*)d_in[2];
    const float* W_ne  = (const float*)d_in[3];
    const float* b_ne  = (const float*)d_in[4];
    const float* W_n   = (const float*)d_in[5];
    const float* b_n   = (const float*)d_in[6];
    const float* W_net = (const float*)d_in[7];
    const float* b_net = (const float*)d_in[8];
    const float* eps   = (const float*)d_in[9];
    float* out = (float*)d_out;

    // 256MB edges pass-through as a driver D2D copy (graph-capturable).
    cudaMemcpyAsync(out + EDGE_OFF, edges,
                    (size_t)NN * NN * EE * sizeof(float),
                    cudaMemcpyDeviceToDevice, 0);

    // Everything else in one small kernel.
    ginconv_compute<<<NN, 256>>>(adj, nodes, edges, W_ne, b_ne, W_n, b_n,
                                 W_net, b_net, eps, out);
}

// round 13
// speedup vs baseline: 1.4471x; 1.4471x over previous
#include <cuda_runtime.h>

// GINConv N=2048, F=32, E=16, K=32, adj density ~5%.
// Output tuple layout: [adj N*N][out N*K][edges N*N*E], all fp32.
//
// Round-12 structure:
//   - edges pass-through: cudaMemcpyAsync D2D (measured ~6.7 TB/s)
//   - pre-kernel: node_part = nodes@W_ne[:F]+b_ne, node_term = relu(nodes@W_n+b_n)
//     for all nodes into __device__ scratch (removes 32 shfls/neighbor)
//   - main kernel (block per row): adj copy + ballot compaction, then sparse
//     message with only 16 edge-shfls per neighbor, 2-way neighbor ILP,
//     epilogue GEMV with L2-resident weights.

#define NN 2048
#define FF 32
#define EE 16
#define KK 32

#define OUT_OFF   ((size_t)NN * NN)
#define EDGE_OFF  ((size_t)NN * NN + (size_t)NN * KK)

__device__ float g_npart[NN * FF];   // nodes @ W_ne[:F] + b_ne
__device__ float g_nterm[NN * FF];   // relu(nodes @ W_n + b_n)

// ---------------- pre-kernel: warp per node row ----------------
__global__ void __launch_bounds__(256) gin_pre(
    const float* __restrict__ nodes, const float* __restrict__ W_ne,
    const float* __restrict__ b_ne,  const float* __restrict__ W_n,
    const float* __restrict__ b_n)
{
    __shared__ float sW1[FF * FF];
    __shared__ float sW2[FF * FF];
    const int tid = threadIdx.x;
    for (int t = tid; t < FF * FF; t += 256) {
        sW1[t] = W_ne[t];           // first F rows of [(F+E),F]
        sW2[t] = W_n[t];
    }
    __syncthreads();

    const int wrp = tid >> 5, lane = tid & 31;
    const int j = blockIdx.x * 8 + wrp;
    float x = nodes[j * FF + lane];
    float p = b_ne[lane];
    float t = b_n[lane];
#pragma unroll
    for (int g = 0; g < FF; ++g) {
        float xv = __shfl_sync(0xffffffffu, x, g);
        p = fmaf(xv, sW1[g * FF + lane], p);
        t = fmaf(xv, sW2[g * FF + lane], t);
    }
    g_npart[j * FF + lane] = p;
    g_nterm[j * FF + lane] = fmaxf(t, 0.f);
}

// ---------------- main kernel: block per graph row ----------------
__global__ void __launch_bounds__(256) gin_main(
    const float* __restrict__ adj,   const float* __restrict__ edges,
    const float* __restrict__ W_ne,  const float* __restrict__ W_net,
    const float* __restrict__ b_net, const float* __restrict__ eps,
    float* __restrict__ out)
{
    __shared__ float sWe[EE * FF];        // edge slice of W_ne     2KB
    __shared__ float spart[8 * FF];       //                        1KB
    __shared__ float spre[FF];
    __shared__ unsigned short snbr[NN];   //                        4KB
    __shared__ int scnt;

    const int tid  = threadIdx.x;
    const int row  = blockIdx.x;
    const int wrp  = tid >> 5;
    const int lane = tid & 31;

    for (int t = tid; t < EE * FF; t += 256) sWe[t] = W_ne[FF * FF + t];
    if (tid == 0) scnt = 0;
    __syncthreads();

    // adj row: streaming copy + warp-ballot compaction (sum is order-free)
    {
        const float4* src = (const float4*)(adj + (size_t)row * NN);
        float4*       dst = (float4*)(out + (size_t)row * NN);
        const unsigned ltmask = (1u << lane) - 1u;
#pragma unroll
        for (int it = 0; it < 2; ++it) {
            int idx = tid + it * 256;
            float4 a = __ldcs(src + idx);
            __stcs(dst + idx, a);
            unsigned m0 = __ballot_sync(0xffffffffu, a.x != 0.f);
            unsigned m1 = __ballot_sync(0xffffffffu, a.y != 0.f);
            unsigned m2 = __ballot_sync(0xffffffffu, a.z != 0.f);
            unsigned m3 = __ballot_sync(0xffffffffu, a.w != 0.f);
            int tot = __popc(m0) + __popc(m1) + __popc(m2) + __popc(m3);
            int base = 0;
            if (lane == 0 && tot) base = atomicAdd(&scnt, tot);
            base = __shfl_sync(0xffffffffu, base, 0);
            int jb = idx * 4;
            if (a.x != 0.f) snbr[base + __popc(m0 & ltmask)] = (unsigned short)(jb);
            base += __popc(m0);
            if (a.y != 0.f) snbr[base + __popc(m1 & ltmask)] = (unsigned short)(jb + 1);
            base += __popc(m1);
            if (a.z != 0.f) snbr[base + __popc(m2 & ltmask)] = (unsigned short)(jb + 2);
            base += __popc(m2);
            if (a.w != 0.f) snbr[base + __popc(m3 & ltmask)] = (unsigned short)(jb + 3);
        }
    }
    __syncthreads();

    // sparse message: warp processes neighbor pairs (n, n+8), lane = feature.
    // per neighbor: 1x 64B edge load, 1x 128B npart load, 16 shfl+fma. ILP-2.
    {
        const int nnz = scnt;
        const float* erow = edges + (size_t)row * NN * EE;
        const int el = lane & (EE - 1);
        float acc = 0.f;
        for (int n = wrp; n < nnz; n += 16) {
            int j0 = snbr[n];
            bool h1 = (n + 8) < nnz;
            int j1 = h1 ? snbr[n + 8] : j0;
            float ev0 = erow[j0 * EE + el];
            float ev1 = erow[j1 * EE + el];
            float s0 = g_npart[j0 * FF + lane];
            float s1 = h1 ? g_npart[j1 * FF + lane] : -1e30f;
#pragma unroll
            for (int e = 0; e < EE; ++e) {
                float w = sWe[e * FF + lane];
                s0 = fmaf(__shfl_sync(0xffffffffu, ev0, e), w, s0);
                s1 = fmaf(__shfl_sync(0xffffffffu, ev1, e), w, s1);
            }
            acc += fmaxf(s0, 0.f) + fmaxf(s1, 0.f);
        }
        spart[wrp * FF + lane] = acc;
    }
    __syncthreads();

    // epilogue on warp 0
    if (wrp == 0) {
        float msg = 0.f;
#pragma unroll
        for (int w = 0; w < 8; ++w) msg += spart[w * FF + lane];
        float nt = g_nterm[(size_t)row * FF + lane];
        spre[lane] = (1.f + __ldg(eps)) * nt + msg;
        __syncwarp();
        float o = __ldg(b_net + lane);
#pragma unroll
        for (int f = 0; f < FF; ++f)
            o = fmaf(spre[f], __ldg(W_net + f * KK + lane), o);
        out[OUT_OFF + (size_t)row * KK + lane] = fmaxf(o, 0.f);
    }
}

extern "C" void kernel_launch(void* const* d_in, const int* in_sizes, int n_in,
                              void* d_out, int out_size)
{
    const float* adj   = (const float*)d_in[0];
    const float* nodes = (const float*)d_in[1];
    const float* edges = (const float*)d_in[2];
    const float* W_ne  = (const float*)d_in[3];
    const float* b_ne  = (const float*)d_in[4];
    const float* W_n   = (const float*)d_in[5];
    const float* b_n   = (const float*)d_in[6];
    const float* W_net = (const float*)d_in[7];
    const float* b_net = (const float*)d_in[8];
    const float* eps   = (const float*)d_in[9];
    float* out = (float*)d_out;

    gin_pre<<<NN / 8, 256>>>(nodes, W_ne, b_ne, W_n, b_n);
    gin_main<<<NN, 256>>>(adj, edges, W_ne, W_net, b_net, eps, out);

    // 256MB edges pass-through as a driver D2D copy (graph-capturable).
    cudaMemcpyAsync(out + EDGE_OFF, edges,
                    (size_t)NN * NN * EE * sizeof(float),
                    cudaMemcpyDeviceToDevice, 0);
}

// round 14
// speedup vs baseline: 1.4495x; 1.0016x over previous
#include <cuda_runtime.h>

// GINConv N=2048, F=32, E=16, K=32, adj density ~5%.
// Output tuple layout: [adj N*N][out N*K][edges N*N*E], all fp32.
//
// Round-13 structure:
//   - 256MB edges pass-through: cudaMemcpyAsync D2D on a FORKED stream
//     (event fork/join so graph capture records a parallel branch; copy
//     runs concurrently with the compute kernels -> compute is hidden).
//   - pre-kernel: node_part/node_term for all nodes into __device__ scratch.
//   - main kernel (block per row): adj copy + ballot compaction, sparse
//     message (16 edge-shfls per neighbor pair, ILP-2), epilogue GEMV.

#define NN 2048
#define FF 32
#define EE 16
#define KK 32

#define OUT_OFF   ((size_t)NN * NN)
#define EDGE_OFF  ((size_t)NN * NN + (size_t)NN * KK)

__device__ float g_npart[NN * FF];   // nodes @ W_ne[:F] + b_ne
__device__ float g_nterm[NN * FF];   // relu(nodes @ W_n + b_n)

// Fork/join plumbing, created once at program init (no device memory).
static cudaStream_t g_copy_stream;
static cudaEvent_t  g_ev_fork, g_ev_join;
static struct GinStreamInit {
    GinStreamInit() {
        cudaStreamCreateWithFlags(&g_copy_stream, cudaStreamNonBlocking);
        cudaEventCreateWithFlags(&g_ev_fork, cudaEventDisableTiming);
        cudaEventCreateWithFlags(&g_ev_join, cudaEventDisableTiming);
    }
} g_gin_stream_init;

// ---------------- pre-kernel: warp per node row ----------------
__global__ void __launch_bounds__(256) gin_pre(
    const float* __restrict__ nodes, const float* __restrict__ W_ne,
    const float* __restrict__ b_ne,  const float* __restrict__ W_n,
    const float* __restrict__ b_n)
{
    __shared__ float sW1[FF * FF];
    __shared__ float sW2[FF * FF];
    const int tid = threadIdx.x;
    for (int t = tid; t < FF * FF; t += 256) {
        sW1[t] = W_ne[t];           // first F rows of [(F+E),F]
        sW2[t] = W_n[t];
    }
    __syncthreads();

    const int wrp = tid >> 5, lane = tid & 31;
    const int j = blockIdx.x * 8 + wrp;
    float x = nodes[j * FF + lane];
    float p = b_ne[lane];
    float t = b_n[lane];
#pragma unroll
    for (int g = 0; g < FF; ++g) {
        float xv = __shfl_sync(0xffffffffu, x, g);
        p = fmaf(xv, sW1[g * FF + lane], p);
        t = fmaf(xv, sW2[g * FF + lane], t);
    }
    g_npart[j * FF + lane] = p;
    g_nterm[j * FF + lane] = fmaxf(t, 0.f);
}

// ---------------- main kernel: block per graph row ----------------
__global__ void __launch_bounds__(256) gin_main(
    const float* __restrict__ adj,   const float* __restrict__ edges,
    const float* __restrict__ W_ne,  const float* __restrict__ W_net,
    const float* __restrict__ b_net, const float* __restrict__ eps,
    float* __restrict__ out)
{
    __shared__ float sWe[EE * FF];        // edge slice of W_ne     2KB
    __shared__ float spart[8 * FF];       //                        1KB
    __shared__ float spre[FF];
    __shared__ unsigned short snbr[NN];   //                        4KB
    __shared__ int scnt;

    const int tid  = threadIdx.x;
    const int row  = blockIdx.x;
    const int wrp  = tid >> 5;
    const int lane = tid & 31;

    for (int t = tid; t < EE * FF; t += 256) sWe[t] = W_ne[FF * FF + t];
    if (tid == 0) scnt = 0;
    __syncthreads();

    // adj row: streaming copy + warp-ballot compaction (sum is order-free)
    {
        const float4* src = (const float4*)(adj + (size_t)row * NN);
        float4*       dst = (float4*)(out + (size_t)row * NN);
        const unsigned ltmask = (1u << lane) - 1u;
#pragma unroll
        for (int it = 0; it < 2; ++it) {
            int idx = tid + it * 256;
            float4 a = __ldcs(src + idx);
            __stcs(dst + idx, a);
            unsigned m0 = __ballot_sync(0xffffffffu, a.x != 0.f);
            unsigned m1 = __ballot_sync(0xffffffffu, a.y != 0.f);
            unsigned m2 = __ballot_sync(0xffffffffu, a.z != 0.f);
            unsigned m3 = __ballot_sync(0xffffffffu, a.w != 0.f);
            int tot = __popc(m0) + __popc(m1) + __popc(m2) + __popc(m3);
            int base = 0;
            if (lane == 0 && tot) base = atomicAdd(&scnt, tot);
            base = __shfl_sync(0xffffffffu, base, 0);
            int jb = idx * 4;
            if (a.x != 0.f) snbr[base + __popc(m0 & ltmask)] = (unsigned short)(jb);
            base += __popc(m0);
            if (a.y != 0.f) snbr[base + __popc(m1 & ltmask)] = (unsigned short)(jb + 1);
            base += __popc(m1);
            if (a.z != 0.f) snbr[base + __popc(m2 & ltmask)] = (unsigned short)(jb + 2);
            base += __popc(m2);
            if (a.w != 0.f) snbr[base + __popc(m3 & ltmask)] = (unsigned short)(jb + 3);
        }
    }
    __syncthreads();

    // sparse message: warp processes neighbor pairs (n, n+8), lane = feature.
    {
        const int nnz = scnt;
        const float* erow = edges + (size_t)row * NN * EE;
        const int el = lane & (EE - 1);
        float acc = 0.f;
        for (int n = wrp; n < nnz; n += 16) {
            int j0 = snbr[n];
            bool h1 = (n + 8) < nnz;
            int j1 = h1 ? snbr[n + 8] : j0;
            float ev0 = erow[j0 * EE + el];
            float ev1 = erow[j1 * EE + el];
            float s0 = g_npart[j0 * FF + lane];
            float s1 = h1 ? g_npart[j1 * FF + lane] : -1e30f;
#pragma unroll
            for (int e = 0; e < EE; ++e) {
                float w = sWe[e * FF + lane];
                s0 = fmaf(__shfl_sync(0xffffffffu, ev0, e), w, s0);
                s1 = fmaf(__shfl_sync(0xffffffffu, ev1, e), w, s1);
            }
            acc += fmaxf(s0, 0.f) + fmaxf(s1, 0.f);
        }
        spart[wrp * FF + lane] = acc;
    }
    __syncthreads();

    // epilogue on warp 0
    if (wrp == 0) {
        float msg = 0.f;
#pragma unroll
        for (int w = 0; w < 8; ++w) msg += spart[w * FF + lane];
        float nt = g_nterm[(size_t)row * FF + lane];
        spre[lane] = (1.f + __ldg(eps)) * nt + msg;
        __syncwarp();
        float o = __ldg(b_net + lane);
#pragma unroll
        for (int f = 0; f < FF; ++f)
            o = fmaf(spre[f], __ldg(W_net + f * KK + lane), o);
        out[OUT_OFF + (size_t)row * KK + lane] = fmaxf(o, 0.f);
    }
}

extern "C" void kernel_launch(void* const* d_in, const int* in_sizes, int n_in,
                              void* d_out, int out_size)
{
    const float* adj   = (const float*)d_in[0];
    const float* nodes = (const float*)d_in[1];
    const float* edges = (const float*)d_in[2];
    const float* W_ne  = (const float*)d_in[3];
    const float* b_ne  = (const float*)d_in[4];
    const float* W_n   = (const float*)d_in[5];
    const float* b_n   = (const float*)d_in[6];
    const float* W_net = (const float*)d_in[7];
    const float* b_net = (const float*)d_in[8];
    const float* eps   = (const float*)d_in[9];
    float* out = (float*)d_out;

    // Fork: copy branch runs the 256MB pass-through concurrently.
    cudaEventRecord(g_ev_fork, 0);
    cudaStreamWaitEvent(g_copy_stream, g_ev_fork, 0);
    cudaMemcpyAsync(out + EDGE_OFF, edges,
                    (size_t)NN * NN * EE * sizeof(float),
                    cudaMemcpyDeviceToDevice, g_copy_stream);
    cudaEventRecord(g_ev_join, g_copy_stream);

    // Compute branch on the main (captured) stream.
    gin_pre<<<NN / 8, 256>>>(nodes, W_ne, b_ne, W_n, b_n);
    gin_main<<<NN, 256>>>(adj, edges, W_ne, W_net, b_net, eps, out);

    // Join: main stream waits for the copy branch.
    cudaStreamWaitEvent(0, g_ev_join, 0);
}

// round 17
// speedup vs baseline: 1.6773x; 1.1572x over previous
#include <cuda_runtime.h>

// GINConv N=2048, F=32, E=16, K=32, adj density ~5%.
// Output tuple layout: [adj N*N][out N*K][edges N*N*E], all fp32.
//
// Round-16 structure: NO streams/events/memcpy. Overlap of the 256MB edges
// pass-through with the sparse compute is done via heterogeneous blocks in
// ONE kernel: blocks 0..511 copy (ILP-4 grid-stride, streaming hints),
// blocks 512..2559 each handle one graph row (adj copy + ballot compaction,
// sparse relu-message, epilogue GEMV). Copy blocks occupy low indices so
// they all start in wave 1 and run for the whole kernel; compute blocks
// stream through the remaining residency slots -> scheduler-guaranteed
// overlap. gin_pre runs first (needs a global barrier before the gather).

#define NN 2048
#define FF 32
#define EE 16
#define KK 32

#define OUT_OFF   ((size_t)NN * NN)
#define EDGE_OFF  ((size_t)NN * NN + (size_t)NN * KK)

#define CP_BLOCKS 512
#define CP_STRIDE ((size_t)CP_BLOCKS * 256)   // 2^17 threads in copy role

__device__ float g_npart[NN * FF];   // nodes @ W_ne[:F] + b_ne
__device__ float g_nterm[NN * FF];   // relu(nodes @ W_n + b_n)

// ---------------- pre-kernel: warp per node row ----------------
__global__ void __launch_bounds__(256) gin_pre(
    const float* __restrict__ nodes, const float* __restrict__ W_ne,
    const float* __restrict__ b_ne,  const float* __restrict__ W_n,
    const float* __restrict__ b_n)
{
    __shared__ float sW1[FF * FF];
    __shared__ float sW2[FF * FF];
    const int tid = threadIdx.x;
    for (int t = tid; t < FF * FF; t += 256) {
        sW1[t] = W_ne[t];           // first F rows of [(F+E),F]
        sW2[t] = W_n[t];
    }
    __syncthreads();

    const int wrp = tid >> 5, lane = tid & 31;
    const int j = blockIdx.x * 8 + wrp;
    float x = nodes[j * FF + lane];
    float p = b_ne[lane];
    float t = b_n[lane];
#pragma unroll
    for (int g = 0; g < FF; ++g) {
        float xv = __shfl_sync(0xffffffffu, x, g);
        p = fmaf(xv, sW1[g * FF + lane], p);
        t = fmaf(xv, sW2[g * FF + lane], t);
    }
    g_npart[j * FF + lane] = p;
    g_nterm[j * FF + lane] = fmaxf(t, 0.f);
}

// ---------------- fused kernel: copy blocks + compute blocks ----------------
__global__ void __launch_bounds__(256) gin_fused(
    const float* __restrict__ adj,   const float* __restrict__ edges,
    const float* __restrict__ W_ne,  const float* __restrict__ W_net,
    const float* __restrict__ b_net, const float* __restrict__ eps,
    float* __restrict__ out)
{
    const int tid = threadIdx.x;

    // ======================= COPY ROLE (blocks 0..511) =======================
    if (blockIdx.x < CP_BLOCKS) {
        const float4* src = (const float4*)edges;
        float4*       dst = (float4*)(out + EDGE_OFF);
        size_t idx = (size_t)blockIdx.x * 256 + tid;
        // 2^24 float4 / 2^17 threads = 128/thread = 32 ILP-4 batches
#pragma unroll 4
        for (int it = 0; it < 32; ++it) {
            float4 r0 = __ldcs(src + idx);
            float4 r1 = __ldcs(src + idx + CP_STRIDE);
            float4 r2 = __ldcs(src + idx + 2 * CP_STRIDE);
            float4 r3 = __ldcs(src + idx + 3 * CP_STRIDE);
            __stcs(dst + idx,                 r0);
            __stcs(dst + idx + CP_STRIDE,     r1);
            __stcs(dst + idx + 2 * CP_STRIDE, r2);
            __stcs(dst + idx + 3 * CP_STRIDE, r3);
            idx += 4 * CP_STRIDE;
        }
        return;
    }

    // ===================== COMPUTE ROLE (one graph row) ======================
    __shared__ float sWe[EE * FF];        // edge slice of W_ne     2KB
    __shared__ float spart[8 * FF];       //                        1KB
    __shared__ float spre[FF];
    __shared__ unsigned short snbr[NN];   //                        4KB
    __shared__ int scnt;

    const int row  = blockIdx.x - CP_BLOCKS;
    const int wrp  = tid >> 5;
    const int lane = tid & 31;

    for (int t = tid; t < EE * FF; t += 256) sWe[t] = W_ne[FF * FF + t];
    if (tid == 0) scnt = 0;
    __syncthreads();

    // adj row: streaming copy + warp-ballot compaction (sum is order-free)
    {
        const float4* src = (const float4*)(adj + (size_t)row * NN);
        float4*       dst = (float4*)(out + (size_t)row * NN);
        const unsigned ltmask = (1u << lane) - 1u;
#pragma unroll
        for (int it = 0; it < 2; ++it) {
            int idx = tid + it * 256;
            float4 a = __ldcs(src + idx);
            __stcs(dst + idx, a);
            unsigned m0 = __ballot_sync(0xffffffffu, a.x != 0.f);
            unsigned m1 = __ballot_sync(0xffffffffu, a.y != 0.f);
            unsigned m2 = __ballot_sync(0xffffffffu, a.z != 0.f);
            unsigned m3 = __ballot_sync(0xffffffffu, a.w != 0.f);
            int tot = __popc(m0) + __popc(m1) + __popc(m2) + __popc(m3);
            int base = 0;
            if (lane == 0 && tot) base = atomicAdd(&scnt, tot);
            base = __shfl_sync(0xffffffffu, base, 0);
            int jb = idx * 4;
            if (a.x != 0.f) snbr[base + __popc(m0 & ltmask)] = (unsigned short)(jb);
            base += __popc(m0);
            if (a.y != 0.f) snbr[base + __popc(m1 & ltmask)] = (unsigned short)(jb + 1);
            base += __popc(m1);
            if (a.z != 0.f) snbr[base + __popc(m2 & ltmask)] = (unsigned short)(jb + 2);
            base += __popc(m2);
            if (a.w != 0.f) snbr[base + __popc(m3 & ltmask)] = (unsigned short)(jb + 3);
        }
    }
    __syncthreads();

    // sparse message: warp processes neighbor pairs (n, n+8), lane = feature.
    {
        const int nnz = scnt;
        const float* erow = edges + (size_t)row * NN * EE;
        const int el = lane & (EE - 1);
        float acc = 0.f;
        for (int n = wrp; n < nnz; n += 16) {
            int j0 = snbr[n];
            bool h1 = (n + 8) < nnz;
            int j1 = h1 ? snbr[n + 8] : j0;
            float ev0 = erow[j0 * EE + el];
            float ev1 = erow[j1 * EE + el];
            float s0 = g_npart[j0 * FF + lane];
            float s1 = h1 ? g_npart[j1 * FF + lane] : -1e30f;
#pragma unroll
            for (int e = 0; e < EE; ++e) {
                float w = sWe[e * FF + lane];
                s0 = fmaf(__shfl_sync(0xffffffffu, ev0, e), w, s0);
                s1 = fmaf(__shfl_sync(0xffffffffu, ev1, e), w, s1);
            }
            acc += fmaxf(s0, 0.f) + fmaxf(s1, 0.f);
        }
        spart[wrp * FF + lane] = acc;
    }
    __syncthreads();

    // epilogue on warp 0
    if (wrp == 0) {
        float msg = 0.f;
#pragma unroll
        for (int w = 0; w < 8; ++w) msg += spart[w * FF + lane];
        float nt = g_nterm[(size_t)row * FF + lane];
        spre[lane] = (1.f + __ldg(eps)) * nt + msg;
        __syncwarp();
        float o = __ldg(b_net + lane);
#pragma unroll
        for (int f = 0; f < FF; ++f)
            o = fmaf(spre[f], __ldg(W_net + f * KK + lane), o);
        out[OUT_OFF + (size_t)row * KK + lane] = fmaxf(o, 0.f);
    }
}

extern "C" void kernel_launch(void* const* d_in, const int* in_sizes, int n_in,
                              void* d_out, int out_size)
{
    const float* adj   = (const float*)d_in[0];
    const float* nodes = (const float*)d_in[1];
    const float* edges = (const float*)d_in[2];
    const float* W_ne  = (const float*)d_in[3];
    const float* b_ne  = (const float*)d_in[4];
    const float* W_n   = (const float*)d_in[5];
    const float* b_n   = (const float*)d_in[6];
    const float* W_net = (const float*)d_in[7];
    const float* b_net = (const float*)d_in[8];
    const float* eps   = (const float*)d_in[9];
    float* out = (float*)d_out;

    gin_pre<<<NN / 8, 256>>>(nodes, W_ne, b_ne, W_n, b_n);
    gin_fused<<<CP_BLOCKS + NN, 256>>>(adj, edges, W_ne, W_net, b_net, eps, out);
}